// round 14
// baseline (speedup 1.0000x reference)
#include <cuda_runtime.h>
#include <math.h>
#include <stdint.h>

// ---------------- problem constants ----------------
#define BB   16
#define WW   32
#define MM   512
#define NHID 64
#define NSEQ 8192   // B*M
#define LOG2E 1.4426950408889634f
#define LN2   0.6931471805599453f

// ---------------- scratch (device globals; no runtime alloc) ----------------
__device__ float g_hid[NSEQ * NHID];
__device__ float g_e1[NSEQ * 32];
__device__ float g_e2[NSEQ * 32];
__device__ float g_amx[NSEQ * 512];        // RAW a_mx (pre-normalization)
__device__ float g_colsq_part[8][NSEQ];    // per-(i-block) partial column sumsq
__device__ float g_invn[NSEQ];
__device__ float g_adjmix[NSEQ * 512];
__device__ float g_rg[NSEQ * 64];
__device__ float g_h1g[NSEQ * 10];

// fast accurate tanh
__device__ __forceinline__ float fast_tanh(float x) {
    x = fminf(fmaxf(x, -10.0f), 10.0f);
    float e = __expf(2.0f * x);
    return __fdividef(e - 1.0f, e + 1.0f);
}

__device__ __forceinline__ float ex2f(float x) {
    float r;
    asm("ex2.approx.f32 %0, %1;" : "=f"(r) : "f"(x));
    return r;
}

__device__ __forceinline__ float f2tf32f(float x) {
    uint32_t r;
    asm("cvt.rna.tf32.f32 %0, %1;" : "=r"(r) : "f"(x));
    return __uint_as_float(r);
}
__device__ __forceinline__ void mma_tf32(float c[4], uint32_t a0, uint32_t a1,
                                         uint32_t a2, uint32_t a3,
                                         uint32_t b0, uint32_t b1) {
    asm volatile(
        "mma.sync.aligned.m16n8k8.row.col.f32.tf32.tf32.f32 "
        "{%0,%1,%2,%3}, {%4,%5,%6,%7}, {%8,%9}, {%0,%1,%2,%3};"
        : "+f"(c[0]), "+f"(c[1]), "+f"(c[2]), "+f"(c[3])
        : "r"(a0), "r"(a1), "r"(a2), "r"(a3), "r"(b0), "r"(b1));
}

// ---------------- K1: warp-autonomous RNN, 2 sequences per warp ----------------
__global__ void __launch_bounds__(128) rnn_kernel(
    const float* __restrict__ x, const float* __restrict__ Wih,
    const float* __restrict__ Whh, const float* __restrict__ bih,
    const float* __restrict__ bhh, const float* __restrict__ W1,
    const float* __restrict__ W2) {
    __shared__ __align__(16) float whh_s[64][68];
    __shared__ __align__(16) float w1_s[32][68];
    __shared__ __align__(16) float w2_s[32][68];
    __shared__ __align__(16) float h_s[4][2][2][64];   // [warp][buf][seq][unit]
    int tid = threadIdx.x;
    int wip = tid >> 5, l = tid & 31;

    for (int i = tid; i < 1024; i += 128) {
        float4 v = ((const float4*)Whh)[i];
        *(float4*)&whh_s[i >> 4][(i & 15) * 4] = v;
    }
    for (int i = tid; i < 512; i += 128) {
        int r = i >> 4, c = (i & 15) * 4;
        *(float4*)&w1_s[r][c] = ((const float4*)W1)[i];
        *(float4*)&w2_s[r][c] = ((const float4*)W2)[i];
    }
    h_s[wip][1][0][l] = 0.0f;  h_s[wip][1][0][l + 32] = 0.0f;
    h_s[wip][1][1][l] = 0.0f;  h_s[wip][1][1][l + 32] = 0.0f;
    __syncthreads();

    int n0 = blockIdx.x * 8 + wip * 2;
    int n1 = n0 + 1;
    int b0 = n0 >> 9, m0 = n0 & 511;
    int b1c = n1 >> 9, m1 = n1 & 511;
    float seqv0 = x[(b0 * 32 + l) * 512 + m0];
    float seqv1 = x[(b1c * 32 + l) * 512 + m1];

    float wA[64], wB[64];
#pragma unroll
    for (int k4 = 0; k4 < 16; k4++) {
        float4 a = *(const float4*)&whh_s[l][k4 * 4];
        wA[k4 * 4 + 0] = a.x; wA[k4 * 4 + 1] = a.y;
        wA[k4 * 4 + 2] = a.z; wA[k4 * 4 + 3] = a.w;
        float4 c = *(const float4*)&whh_s[l + 32][k4 * 4];
        wB[k4 * 4 + 0] = c.x; wB[k4 * 4 + 1] = c.y;
        wB[k4 * 4 + 2] = c.z; wB[k4 * 4 + 3] = c.w;
    }
    float wihA = Wih[l], wihB = Wih[l + 32];
    float biasA = bih[l] + bhh[l], biasB = bih[l + 32] + bhh[l + 32];

    int p = 1;
    float h_lo0 = 0.0f, h_hi0 = 0.0f, h_lo1 = 0.0f, h_hi1 = 0.0f;
#pragma unroll 1
    for (int t = 0; t < 32; t++) {
        float xt0 = __shfl_sync(0xffffffffu, seqv0, t);
        float xt1 = __shfl_sync(0xffffffffu, seqv1, t);
        float a00 = fmaf(xt0, wihA, biasA), a01 = 0.0f;
        float b00 = fmaf(xt0, wihB, biasB), b01 = 0.0f;
        float a10 = fmaf(xt1, wihA, biasA), a11 = 0.0f;
        float b10 = fmaf(xt1, wihB, biasB), b11 = 0.0f;
        const float4* hp0 = (const float4*)h_s[wip][p][0];
        const float4* hp1 = (const float4*)h_s[wip][p][1];
#pragma unroll
        for (int k4 = 0; k4 < 16; k4++) {
            float4 h0 = hp0[k4];
            float4 h1 = hp1[k4];
            int base = k4 * 4;
            if (k4 & 1) {
                a01 = fmaf(h0.x, wA[base + 0], a01); a01 = fmaf(h0.y, wA[base + 1], a01);
                a01 = fmaf(h0.z, wA[base + 2], a01); a01 = fmaf(h0.w, wA[base + 3], a01);
                b01 = fmaf(h0.x, wB[base + 0], b01); b01 = fmaf(h0.y, wB[base + 1], b01);
                b01 = fmaf(h0.z, wB[base + 2], b01); b01 = fmaf(h0.w, wB[base + 3], b01);
                a11 = fmaf(h1.x, wA[base + 0], a11); a11 = fmaf(h1.y, wA[base + 1], a11);
                a11 = fmaf(h1.z, wA[base + 2], a11); a11 = fmaf(h1.w, wA[base + 3], a11);
                b11 = fmaf(h1.x, wB[base + 0], b11); b11 = fmaf(h1.y, wB[base + 1], b11);
                b11 = fmaf(h1.z, wB[base + 2], b11); b11 = fmaf(h1.w, wB[base + 3], b11);
            } else {
                a00 = fmaf(h0.x, wA[base + 0], a00); a00 = fmaf(h0.y, wA[base + 1], a00);
                a00 = fmaf(h0.z, wA[base + 2], a00); a00 = fmaf(h0.w, wA[base + 3], a00);
                b00 = fmaf(h0.x, wB[base + 0], b00); b00 = fmaf(h0.y, wB[base + 1], b00);
                b00 = fmaf(h0.z, wB[base + 2], b00); b00 = fmaf(h0.w, wB[base + 3], b00);
                a10 = fmaf(h1.x, wA[base + 0], a10); a10 = fmaf(h1.y, wA[base + 1], a10);
                a10 = fmaf(h1.z, wA[base + 2], a10); a10 = fmaf(h1.w, wA[base + 3], a10);
                b10 = fmaf(h1.x, wB[base + 0], b10); b10 = fmaf(h1.y, wB[base + 1], b10);
                b10 = fmaf(h1.z, wB[base + 2], b10); b10 = fmaf(h1.w, wB[base + 3], b10);
            }
        }
        h_lo0 = fast_tanh(a00 + a01);
        h_hi0 = fast_tanh(b00 + b01);
        h_lo1 = fast_tanh(a10 + a11);
        h_hi1 = fast_tanh(b10 + b11);
        p ^= 1;
        h_s[wip][p][0][l]      = h_lo0;
        h_s[wip][p][0][l + 32] = h_hi0;
        h_s[wip][p][1][l]      = h_lo1;
        h_s[wip][p][1][l + 32] = h_hi1;
        __syncwarp();
    }
    g_hid[n0 * 64 + l]      = h_lo0;
    g_hid[n0 * 64 + l + 32] = h_hi0;
    g_hid[n1 * 64 + l]      = h_lo1;
    g_hid[n1 * 64 + l + 32] = h_hi1;

    const float* hr0 = h_s[wip][p][0];
    const float* hr1 = h_s[wip][p][1];
    float e10 = 0.0f, e20 = 0.0f, e11 = 0.0f, e21 = 0.0f;
#pragma unroll
    for (int k = 0; k < 64; k++) {
        float w1v = w1_s[l][k], w2v = w2_s[l][k];
        float h0 = hr0[k], h1 = hr1[k];
        e10 = fmaf(h0, w1v, e10);
        e20 = fmaf(h0, w2v, e20);
        e11 = fmaf(h1, w1v, e11);
        e21 = fmaf(h1, w2v, e21);
    }
    g_e1[n0 * 32 + l] = e10;
    g_e2[n0 * 32 + l] = e20;
    g_e1[n1 * 32 + l] = e11;
    g_e2[n1 * 32 + l] = e21;
}

// ---------------- K2: attention, branch-free rescaled elu ----------------
__global__ void __launch_bounds__(256) attn_kernel(
    const float* __restrict__ b1, const float* __restrict__ V,
    const float* __restrict__ bv) {
    int b  = blockIdx.z;
    int i0 = blockIdx.y * 64, j0 = blockIdx.x * 64;
    __shared__ float e2s[64][33], e1s[64][33];
    __shared__ float part[16][65];
    __shared__ float Vs[32];
    int tid = threadIdx.x;
    if (tid < 32) Vs[tid] = V[tid];
#pragma unroll
    for (int it = 0; it < 2; it++) {
        int idx = tid + it * 256;          // 0..511
        int r = idx >> 3, c4 = (idx & 7) * 4;
        float4 v2 = *(const float4*)&g_e2[(b * 512 + i0 + r) * 32 + c4];
        float4 vb = *(const float4*)&b1[c4];
        e2s[r][c4 + 0] = (v2.x + vb.x) * LOG2E;
        e2s[r][c4 + 1] = (v2.y + vb.y) * LOG2E;
        e2s[r][c4 + 2] = (v2.z + vb.z) * LOG2E;
        e2s[r][c4 + 3] = (v2.w + vb.w) * LOG2E;
        float4 v1 = *(const float4*)&g_e1[(b * 512 + j0 + r) * 32 + c4];
        e1s[r][c4 + 0] = v1.x * LOG2E; e1s[r][c4 + 1] = v1.y * LOG2E;
        e1s[r][c4 + 2] = v1.z * LOG2E; e1s[r][c4 + 3] = v1.w * LOG2E;
    }
    __syncthreads();

    float sumV = 0.0f;
#pragma unroll
    for (int h = 0; h < 32; h++) sumV += Vs[h];

    int tx = tid & 15, ty = tid >> 4;
    float accM[4][4], accE[4][4];
#pragma unroll
    for (int u = 0; u < 4; u++)
#pragma unroll
        for (int v = 0; v < 4; v++) { accM[u][v] = 0.0f; accE[u][v] = 0.0f; }

#pragma unroll 4
    for (int h = 0; h < 32; h++) {
        float av[4], bw[4], vh = Vs[h];
#pragma unroll
        for (int u = 0; u < 4; u++) av[u] = e2s[ty * 4 + u][h];
#pragma unroll
        for (int v = 0; v < 4; v++) bw[v] = e1s[tx * 4 + v][h];
#pragma unroll
        for (int u = 0; u < 4; u++)
#pragma unroll
            for (int v = 0; v < 4; v++) {
                float t = av[u] + bw[v];             // scaled by log2e
                float tp = fmaxf(t, 0.0f);
                float tn = fminf(t, 0.0f);
                float ex = ex2f(tn);
                accM[u][v] = fmaf(tp, vh, accM[u][v]);
                accE[u][v] = fmaf(ex, vh, accE[u][v]);
            }
    }
    float bias2 = bv[0] - sumV;
    float sq[4] = {0.0f, 0.0f, 0.0f, 0.0f};
#pragma unroll
    for (int u = 0; u < 4; u++) {
        float4 o;
        o.x = fmaf(accM[u][0], LN2, accE[u][0]) + bias2;
        o.y = fmaf(accM[u][1], LN2, accE[u][1]) + bias2;
        o.z = fmaf(accM[u][2], LN2, accE[u][2]) + bias2;
        o.w = fmaf(accM[u][3], LN2, accE[u][3]) + bias2;
        sq[0] = fmaf(o.x, o.x, sq[0]); sq[1] = fmaf(o.y, o.y, sq[1]);
        sq[2] = fmaf(o.z, o.z, sq[2]); sq[3] = fmaf(o.w, o.w, sq[3]);
        int i = i0 + ty * 4 + u;
        *(float4*)&g_amx[(b * 512 + i) * 512 + j0 + tx * 4] = o;
    }
#pragma unroll
    for (int v = 0; v < 4; v++) part[ty][tx * 4 + v] = sq[v];
    __syncthreads();
    if (tid < 64) {
        float s = 0.0f;
#pragma unroll
        for (int r = 0; r < 16; r++) s += part[r][tid];
        g_colsq_part[blockIdx.y][b * 512 + j0 + tid] = s;   // no atomics
    }
}

// ---------------- K3: inverse column norms (sum 8 partials) ----------------
__global__ void invnorm_kernel() {
    int i = blockIdx.x * 256 + threadIdx.x;
    float s = 0.0f;
#pragma unroll
    for (int r = 0; r < 8; r++) s += g_colsq_part[r][i];
    g_invn[i] = 1.0f / fmaxf(sqrtf(s), 1e-12f);
}

// ---------------- K5: tf32 mma.sync GEMM, normalization+cvt folded at smem store ----------------
#define APITCH 20
#define BPITCH 132
__global__ void __launch_bounds__(256) gemm_tc_kernel(
    const float* __restrict__ Wb, const float* __restrict__ wb,
    const float* __restrict__ adj) {
    __shared__ float As_hi[128][APITCH];
    __shared__ float Bs_hi[16][BPITCH];
    __shared__ float inv_sh[512];
    int tid = threadIdx.x;
    int n0 = blockIdx.y * 128, j0 = blockIdx.x * 128;
    int b = blockIdx.y >> 2;
    int wid = tid >> 5, lane = tid & 31;
    int warp_row = (wid >> 2) * 64;   // 0 or 64
    int warp_col = (wid & 3) * 32;    // 0..96
    int group = lane >> 2, tig = lane & 3;

    for (int t = tid; t < 512; t += 256) inv_sh[t] = g_invn[b * 512 + t];

    float c[4][4][4];
#pragma unroll
    for (int mt = 0; mt < 4; mt++)
#pragma unroll
        for (int nt = 0; nt < 4; nt++)
#pragma unroll
            for (int q = 0; q < 4; q++) c[mt][nt][q] = 0.0f;

    int ar0 = tid >> 2, ac4 = (tid & 3) * 4;
    int br0 = tid >> 5, bc4 = (tid & 31) * 4;
    float4 vah0 = *(const float4*)&g_amx[(n0 + ar0) * 512 + ac4];
    float4 vah1 = *(const float4*)&g_amx[(n0 + ar0 + 64) * 512 + ac4];
    float4 vbh0 = *(const float4*)&Wb[br0 * 512 + j0 + bc4];
    float4 vbh1 = *(const float4*)&Wb[(br0 + 8) * 512 + j0 + bc4];
    __syncthreads();   // inv_sh ready

    for (int kt = 0; kt < 32; kt++) {
        // A: normalize by column norm (abs k = kt*16 + ac4 + q), cvt to tf32
        float4 iv = *(const float4*)&inv_sh[kt * 16 + ac4];
        As_hi[ar0][ac4 + 0]      = f2tf32f(vah0.x * iv.x);
        As_hi[ar0][ac4 + 1]      = f2tf32f(vah0.y * iv.y);
        As_hi[ar0][ac4 + 2]      = f2tf32f(vah0.z * iv.z);
        As_hi[ar0][ac4 + 3]      = f2tf32f(vah0.w * iv.w);
        As_hi[ar0 + 64][ac4 + 0] = f2tf32f(vah1.x * iv.x);
        As_hi[ar0 + 64][ac4 + 1] = f2tf32f(vah1.y * iv.y);
        As_hi[ar0 + 64][ac4 + 2] = f2tf32f(vah1.z * iv.z);
        As_hi[ar0 + 64][ac4 + 3] = f2tf32f(vah1.w * iv.w);
        Bs_hi[br0][bc4 + 0]      = f2tf32f(vbh0.x);
        Bs_hi[br0][bc4 + 1]      = f2tf32f(vbh0.y);
        Bs_hi[br0][bc4 + 2]      = f2tf32f(vbh0.z);
        Bs_hi[br0][bc4 + 3]      = f2tf32f(vbh0.w);
        Bs_hi[br0 + 8][bc4 + 0]  = f2tf32f(vbh1.x);
        Bs_hi[br0 + 8][bc4 + 1]  = f2tf32f(vbh1.y);
        Bs_hi[br0 + 8][bc4 + 2]  = f2tf32f(vbh1.z);
        Bs_hi[br0 + 8][bc4 + 3]  = f2tf32f(vbh1.w);
        __syncthreads();
        if (kt < 31) {
            int kn = (kt + 1) * 16;
            vah0 = *(const float4*)&g_amx[(n0 + ar0) * 512 + kn + ac4];
            vah1 = *(const float4*)&g_amx[(n0 + ar0 + 64) * 512 + kn + ac4];
            vbh0 = *(const float4*)&Wb[(kn + br0) * 512 + j0 + bc4];
            vbh1 = *(const float4*)&Wb[(kn + br0 + 8) * 512 + j0 + bc4];
        }
#pragma unroll
        for (int s = 0; s < 2; s++) {
            int ks = s * 8;
            uint32_t bh[4][2];
#pragma unroll
            for (int nt = 0; nt < 4; nt++) {
                int nn = warp_col + nt * 8 + group;
                bh[nt][0] = __float_as_uint(Bs_hi[ks + tig][nn]);
                bh[nt][1] = __float_as_uint(Bs_hi[ks + tig + 4][nn]);
            }
#pragma unroll
            for (int mt = 0; mt < 4; mt++) {
                int rr = warp_row + mt * 16 + group;
                uint32_t ah0 = __float_as_uint(As_hi[rr][ks + tig]);
                uint32_t ah1 = __float_as_uint(As_hi[rr + 8][ks + tig]);
                uint32_t ah2 = __float_as_uint(As_hi[rr][ks + tig + 4]);
                uint32_t ah3 = __float_as_uint(As_hi[rr + 8][ks + tig + 4]);
#pragma unroll
                for (int nt = 0; nt < 4; nt++)
                    mma_tf32(c[mt][nt], ah0, ah1, ah2, ah3, bh[nt][0], bh[nt][1]);
            }
        }
        __syncthreads();
    }

    float wbv = wb[0];
#pragma unroll
    for (int mt = 0; mt < 4; mt++) {
#pragma unroll
        for (int nt = 0; nt < 4; nt++) {
            int col = j0 + warp_col + nt * 8 + tig * 2;
            float i0v = inv_sh[col], i1v = inv_sh[col + 1];
#pragma unroll
            for (int half = 0; half < 2; half++) {
                int row = n0 + warp_row + mt * 16 + group + half * 8;
                float d0 = c[mt][nt][half * 2 + 0];
                float d1 = c[mt][nt][half * 2 + 1];
                float2 am = *(const float2*)&g_amx[row * 512 + col];
                float2 ad = *(const float2*)&adj[(row & 511) * 512 + col];
                float s0 = 1.0f / (1.0f + __expf(-(d0 + wbv)));
                float s1 = 1.0f / (1.0f + __expf(-(d1 + wbv)));
                float2 o;
                o.x = fmaf(ad.x, s0, am.x * i0v * (1.0f - s0));
                o.y = fmaf(ad.y, s1, am.y * i1v * (1.0f - s1));
                *(float2*)&g_adjmix[row * 512 + col] = o;
            }
        }
    }
}

// ---------------- K6: fused conv features + rg = relu(r) @ gc1_w ----------------
__global__ void __launch_bounds__(256) convrg_kernel(
    const float* __restrict__ x, const float* __restrict__ conv_w,
    const float* __restrict__ conv_b, const float* __restrict__ convl_w,
    const float* __restrict__ convl_b, const float* __restrict__ gc1_w) {
    __shared__ float cw[256], clw[128], cb[8], clb[8];
    __shared__ float seq[4][32];
    __shared__ float r_sh[4][24];
    __shared__ float g1s[24 * 64];
    int tid = threadIdx.x;
    cw[tid] = conv_w[tid];
    if (tid < 128) clw[tid] = convl_w[tid];
    if (tid < 8) { cb[tid] = conv_b[tid]; clb[tid] = convl_b[tid]; }
    for (int t = tid; t < 24 * 64; t += 256) g1s[t] = gc1_w[t];
    if (tid < 128) {
        int gg = tid >> 5, t = tid & 31;
        int nn = blockIdx.x * 4 + gg;
        seq[gg][t] = x[((nn >> 9) * WW + t) * MM + (nn & 511)];
    }
    __syncthreads();

    if (tid < 96) {
        int g = tid / 24, idx = tid % 24;
        int kk = idx / 3, cc = idx % 3;
        float a;
        if (cc == 0) {
            a = cb[kk];
#pragma unroll
            for (int t = 0; t < 32; t++) a = fmaf(seq[g][t], cw[kk * 32 + t], a);
        } else {
            a = clb[kk];
#pragma unroll
            for (int i = 0; i < 16; i++)
                a = fmaf(seq[g][2 * i + (cc - 1)], clw[kk * 16 + i], a);
        }
        r_sh[g][idx] = fmaxf(a, 0.0f);
    }
    __syncthreads();

    int g = tid >> 6, j = tid & 63;
    int n = blockIdx.x * 4 + g;
    float acc = 0.0f;
#pragma unroll
    for (int idx = 0; idx < 24; idx++)
        acc = fmaf(r_sh[g][idx], g1s[idx * 64 + j], acc);
    g_rg[n * 64 + j] = acc;
}

// ---------------- K8: h1 = relu(adj_mix @ rg + gc1_b); fused h1g = h1 @ gc2_w ----------------
__global__ void __launch_bounds__(256) h1_kernel(
    const float* __restrict__ gc1_b, const float* __restrict__ gc2_w) {
    __shared__ __align__(16) float As[16][68];
    __shared__ __align__(16) float Bs[16][68];
    __shared__ float h1s[64][65];
    __shared__ float g2s[640];
    int tid = threadIdx.x;
    int bb = blockIdx.y;
    int i0 = blockIdx.x * 64;
    int tx = tid & 15, ty = tid >> 4;
    float acc[4][4];
#pragma unroll
    for (int u = 0; u < 4; u++)
#pragma unroll
        for (int v = 0; v < 4; v++) acc[u][v] = 0.0f;
    for (int t = tid; t < 640; t += 256) g2s[t] = gc2_w[t];

    int arow = tid >> 2, ac4 = (tid & 3) * 4;
    int brow = tid >> 4, bc4 = (tid & 15) * 4;
    float4 av  = *(const float4*)&g_adjmix[(bb * 512 + i0 + arow) * 512 + ac4];
    float4 bvv = *(const float4*)&g_rg[(bb * 512 + brow) * 64 + bc4];
    for (int kt = 0; kt < 32; kt++) {
        __syncthreads();
        As[ac4 + 0][arow] = av.x; As[ac4 + 1][arow] = av.y;
        As[ac4 + 2][arow] = av.z; As[ac4 + 3][arow] = av.w;
        *(float4*)&Bs[brow][bc4] = bvv;
        __syncthreads();
        if (kt < 31) {
            int k0 = (kt + 1) * 16;
            av  = *(const float4*)&g_adjmix[(bb * 512 + i0 + arow) * 512 + k0 + ac4];
            bvv = *(const float4*)&g_rg[(bb * 512 + k0 + brow) * 64 + bc4];
        }
#pragma unroll
        for (int k = 0; k < 16; k++) {
            float4 a = *(const float4*)&As[k][ty * 4];
            float4 b = *(const float4*)&Bs[k][tx * 4];
            float a_[4] = {a.x, a.y, a.z, a.w};
            float b_[4] = {b.x, b.y, b.z, b.w};
#pragma unroll
            for (int u = 0; u < 4; u++)
#pragma unroll
                for (int v = 0; v < 4; v++)
                    acc[u][v] = fmaf(a_[u], b_[v], acc[u][v]);
        }
    }
    __syncthreads();
#pragma unroll
    for (int u = 0; u < 4; u++)
#pragma unroll
        for (int v = 0; v < 4; v++)
            h1s[ty * 4 + u][tx * 4 + v] = fmaxf(acc[u][v] + gc1_b[tx * 4 + v], 0.0f);
    __syncthreads();
    for (int idx = tid; idx < 640; idx += 256) {
        int i = idx & 63, jj = idx >> 6;
        float a = 0.0f;
#pragma unroll
        for (int j = 0; j < 64; j++) a = fmaf(h1s[i][j], g2s[j * 10 + jj], a);
        g_h1g[(bb * 512 + i0 + i) * 10 + jj] = a;
    }
}

// ---------------- K9: out_spatial + fused output head ----------------
__global__ void __launch_bounds__(640) out_kernel(
    const float* __restrict__ gc2_b, const float* __restrict__ out_w,
    const float* __restrict__ out_b, float* __restrict__ out) {
    __shared__ float adjs[64][65];
    __shared__ float hgs[64][12];
    __shared__ float oss[64][13];
    __shared__ float hids[64][65];
    __shared__ float ows[592];
    __shared__ float gbs[10], obs[8];
    int tid = threadIdx.x;
    int bb = blockIdx.y;
    int i0 = blockIdx.x * 64;
    for (int t = tid; t < 592; t += 640) ows[t] = out_w[t];
    if (tid < 10) gbs[tid] = gc2_b[tid];
    if (tid < 8)  obs[tid] = out_b[tid];

    int il = tid / 10;
    int jj = tid % 10;
    float acc = 0.0f;
    for (int kt = 0; kt < 8; kt++) {
        __syncthreads();
        for (int idx = tid; idx < 4096; idx += 640) {
            int r = idx >> 6, cc = idx & 63;
            adjs[r][cc] = g_adjmix[(bb * 512 + i0 + r) * 512 + kt * 64 + cc];
        }
        {
            int kr = tid / 10, j2 = tid % 10;
            hgs[kr][j2] = g_h1g[(bb * 512 + kt * 64 + kr) * 10 + j2];
        }
        __syncthreads();
#pragma unroll 8
        for (int k = 0; k < 64; k++) acc = fmaf(adjs[il][k], hgs[k][jj], acc);
    }
    __syncthreads();
    oss[il][jj] = fmaxf(acc + gbs[jj], 0.0f);
    for (int idx = tid; idx < 4096; idx += 640) {
        int r = idx >> 6, cc = idx & 63;
        hids[r][cc] = g_hid[(bb * 512 + i0 + r) * 64 + cc];
    }
    __syncthreads();
    if (tid < 512) {
        int h = tid >> 6, i = tid & 63;
        float a = obs[h];
#pragma unroll
        for (int q = 0; q < 10; q++) a = fmaf(oss[i][q], ows[h * 74 + q], a);
#pragma unroll
        for (int t = 0; t < 64; t++) a = fmaf(hids[i][t], ows[h * 74 + 10 + t], a);
        out[bb * 4096 + h * 512 + i0 + i] = a;
    }
}

// ---------------- launch ----------------
extern "C" void kernel_launch(void* const* d_in, const int* in_sizes, int n_in,
                              void* d_out, int out_size) {
    const float* x       = (const float*)d_in[0];
    const float* adj     = (const float*)d_in[1];
    const float* Wih     = (const float*)d_in[2];
    const float* Whh     = (const float*)d_in[3];
    const float* bih     = (const float*)d_in[4];
    const float* bhh     = (const float*)d_in[5];
    const float* W1      = (const float*)d_in[6];
    const float* W2      = (const float*)d_in[7];
    const float* b1      = (const float*)d_in[8];
    const float* V       = (const float*)d_in[9];
    const float* bv      = (const float*)d_in[10];
    const float* Wb      = (const float*)d_in[11];
    const float* wb      = (const float*)d_in[12];
    const float* conv_w  = (const float*)d_in[13];
    const float* conv_b  = (const float*)d_in[14];
    const float* convl_w = (const float*)d_in[15];
    const float* convl_b = (const float*)d_in[16];
    const float* gc1_w   = (const float*)d_in[17];
    const float* gc1_b   = (const float*)d_in[18];
    const float* gc2_w   = (const float*)d_in[19];
    const float* gc2_b   = (const float*)d_in[20];
    const float* out_w   = (const float*)d_in[21];
    const float* out_b   = (const float*)d_in[22];
    float* out = (float*)d_out;

    // gemm_tc in profiled slot (#4); split kernels folded into gemm.
    rnn_kernel<<<1024, 128>>>(x, Wih, Whh, bih, bhh, W1, W2);
    attn_kernel<<<dim3(8, 8, 16), 256>>>(b1, V, bv);
    invnorm_kernel<<<32, 256>>>();
    gemm_tc_kernel<<<dim3(4, 64), 256>>>(Wb, wb, adj);
    convrg_kernel<<<2048, 256>>>(x, conv_w, conv_b, convl_w, convl_b, gc1_w);
    h1_kernel<<<dim3(8, 16), 256>>>(gc1_b, gc2_w);
    out_kernel<<<dim3(8, 16), 640>>>(gc2_b, out_w, out_b, out);
}

// round 16
// speedup vs baseline: 1.0015x; 1.0015x over previous
#include <cuda_runtime.h>
#include <math.h>
#include <stdint.h>

// ---------------- problem constants ----------------
#define BB   16
#define WW   32
#define MM   512
#define NHID 64
#define NSEQ 8192   // B*M
#define LOG2E 1.4426950408889634f
#define LN2   0.6931471805599453f

// ---------------- scratch (device globals; no runtime alloc) ----------------
__device__ float g_hid[NSEQ * NHID];
__device__ float g_e1[NSEQ * 32];
__device__ float g_e2[NSEQ * 32];
__device__ float g_amx[NSEQ * 512];        // RAW a_mx (pre-normalization)
__device__ float g_colsq_part[8][NSEQ];    // per-(i-block) partial column sumsq
__device__ float g_invn[NSEQ];
__device__ float g_adjmix[NSEQ * 512];
__device__ float g_rg[NSEQ * 64];
__device__ float g_h1g[NSEQ * 10];

// fast accurate tanh
__device__ __forceinline__ float fast_tanh(float x) {
    x = fminf(fmaxf(x, -10.0f), 10.0f);
    float e = __expf(2.0f * x);
    return __fdividef(e - 1.0f, e + 1.0f);
}

__device__ __forceinline__ float ex2f(float x) {
    float r;
    asm("ex2.approx.f32 %0, %1;" : "=f"(r) : "f"(x));
    return r;
}

__device__ __forceinline__ float f2tf32f(float x) {
    uint32_t r;
    asm("cvt.rna.tf32.f32 %0, %1;" : "=r"(r) : "f"(x));
    return __uint_as_float(r);
}
__device__ __forceinline__ void mma_tf32(float c[4], uint32_t a0, uint32_t a1,
                                         uint32_t a2, uint32_t a3,
                                         uint32_t b0, uint32_t b1) {
    asm volatile(
        "mma.sync.aligned.m16n8k8.row.col.f32.tf32.tf32.f32 "
        "{%0,%1,%2,%3}, {%4,%5,%6,%7}, {%8,%9}, {%0,%1,%2,%3};"
        : "+f"(c[0]), "+f"(c[1]), "+f"(c[2]), "+f"(c[3])
        : "r"(a0), "r"(a1), "r"(a2), "r"(a3), "r"(b0), "r"(b1));
}

// ---------------- K1: warp-autonomous RNN, 2 sequences per warp ----------------
__global__ void __launch_bounds__(128) rnn_kernel(
    const float* __restrict__ x, const float* __restrict__ Wih,
    const float* __restrict__ Whh, const float* __restrict__ bih,
    const float* __restrict__ bhh, const float* __restrict__ W1,
    const float* __restrict__ W2) {
    __shared__ __align__(16) float whh_s[64][68];
    __shared__ __align__(16) float w1_s[32][68];
    __shared__ __align__(16) float w2_s[32][68];
    __shared__ __align__(16) float h_s[4][2][2][64];   // [warp][buf][seq][unit]
    int tid = threadIdx.x;
    int wip = tid >> 5, l = tid & 31;

    for (int i = tid; i < 1024; i += 128) {
        float4 v = ((const float4*)Whh)[i];
        *(float4*)&whh_s[i >> 4][(i & 15) * 4] = v;
    }
    for (int i = tid; i < 512; i += 128) {
        int r = i >> 4, c = (i & 15) * 4;
        *(float4*)&w1_s[r][c] = ((const float4*)W1)[i];
        *(float4*)&w2_s[r][c] = ((const float4*)W2)[i];
    }
    h_s[wip][1][0][l] = 0.0f;  h_s[wip][1][0][l + 32] = 0.0f;
    h_s[wip][1][1][l] = 0.0f;  h_s[wip][1][1][l + 32] = 0.0f;
    __syncthreads();

    int n0 = blockIdx.x * 8 + wip * 2;
    int n1 = n0 + 1;
    int b0 = n0 >> 9, m0 = n0 & 511;
    int b1c = n1 >> 9, m1 = n1 & 511;
    float seqv0 = x[(b0 * 32 + l) * 512 + m0];
    float seqv1 = x[(b1c * 32 + l) * 512 + m1];

    float wA[64], wB[64];
#pragma unroll
    for (int k4 = 0; k4 < 16; k4++) {
        float4 a = *(const float4*)&whh_s[l][k4 * 4];
        wA[k4 * 4 + 0] = a.x; wA[k4 * 4 + 1] = a.y;
        wA[k4 * 4 + 2] = a.z; wA[k4 * 4 + 3] = a.w;
        float4 c = *(const float4*)&whh_s[l + 32][k4 * 4];
        wB[k4 * 4 + 0] = c.x; wB[k4 * 4 + 1] = c.y;
        wB[k4 * 4 + 2] = c.z; wB[k4 * 4 + 3] = c.w;
    }
    float wihA = Wih[l], wihB = Wih[l + 32];
    float biasA = bih[l] + bhh[l], biasB = bih[l + 32] + bhh[l + 32];

    int p = 1;
    float h_lo0 = 0.0f, h_hi0 = 0.0f, h_lo1 = 0.0f, h_hi1 = 0.0f;
#pragma unroll 1
    for (int t = 0; t < 32; t++) {
        float xt0 = __shfl_sync(0xffffffffu, seqv0, t);
        float xt1 = __shfl_sync(0xffffffffu, seqv1, t);
        float a00 = fmaf(xt0, wihA, biasA), a01 = 0.0f;
        float b00 = fmaf(xt0, wihB, biasB), b01 = 0.0f;
        float a10 = fmaf(xt1, wihA, biasA), a11 = 0.0f;
        float b10 = fmaf(xt1, wihB, biasB), b11 = 0.0f;
        const float4* hp0 = (const float4*)h_s[wip][p][0];
        const float4* hp1 = (const float4*)h_s[wip][p][1];
#pragma unroll
        for (int k4 = 0; k4 < 16; k4++) {
            float4 h0 = hp0[k4];
            float4 h1 = hp1[k4];
            int base = k4 * 4;
            if (k4 & 1) {
                a01 = fmaf(h0.x, wA[base + 0], a01); a01 = fmaf(h0.y, wA[base + 1], a01);
                a01 = fmaf(h0.z, wA[base + 2], a01); a01 = fmaf(h0.w, wA[base + 3], a01);
                b01 = fmaf(h0.x, wB[base + 0], b01); b01 = fmaf(h0.y, wB[base + 1], b01);
                b01 = fmaf(h0.z, wB[base + 2], b01); b01 = fmaf(h0.w, wB[base + 3], b01);
                a11 = fmaf(h1.x, wA[base + 0], a11); a11 = fmaf(h1.y, wA[base + 1], a11);
                a11 = fmaf(h1.z, wA[base + 2], a11); a11 = fmaf(h1.w, wA[base + 3], a11);
                b11 = fmaf(h1.x, wB[base + 0], b11); b11 = fmaf(h1.y, wB[base + 1], b11);
                b11 = fmaf(h1.z, wB[base + 2], b11); b11 = fmaf(h1.w, wB[base + 3], b11);
            } else {
                a00 = fmaf(h0.x, wA[base + 0], a00); a00 = fmaf(h0.y, wA[base + 1], a00);
                a00 = fmaf(h0.z, wA[base + 2], a00); a00 = fmaf(h0.w, wA[base + 3], a00);
                b00 = fmaf(h0.x, wB[base + 0], b00); b00 = fmaf(h0.y, wB[base + 1], b00);
                b00 = fmaf(h0.z, wB[base + 2], b00); b00 = fmaf(h0.w, wB[base + 3], b00);
                a10 = fmaf(h1.x, wA[base + 0], a10); a10 = fmaf(h1.y, wA[base + 1], a10);
                a10 = fmaf(h1.z, wA[base + 2], a10); a10 = fmaf(h1.w, wA[base + 3], a10);
                b10 = fmaf(h1.x, wB[base + 0], b10); b10 = fmaf(h1.y, wB[base + 1], b10);
                b10 = fmaf(h1.w, wB[base + 3], b10); b10 = fmaf(h1.z, wB[base + 2], b10);
            }
        }
        h_lo0 = fast_tanh(a00 + a01);
        h_hi0 = fast_tanh(b00 + b01);
        h_lo1 = fast_tanh(a10 + a11);
        h_hi1 = fast_tanh(b10 + b11);
        p ^= 1;
        h_s[wip][p][0][l]      = h_lo0;
        h_s[wip][p][0][l + 32] = h_hi0;
        h_s[wip][p][1][l]      = h_lo1;
        h_s[wip][p][1][l + 32] = h_hi1;
        __syncwarp();
    }
    g_hid[n0 * 64 + l]      = h_lo0;
    g_hid[n0 * 64 + l + 32] = h_hi0;
    g_hid[n1 * 64 + l]      = h_lo1;
    g_hid[n1 * 64 + l + 32] = h_hi1;

    const float* hr0 = h_s[wip][p][0];
    const float* hr1 = h_s[wip][p][1];
    float e10 = 0.0f, e20 = 0.0f, e11 = 0.0f, e21 = 0.0f;
#pragma unroll
    for (int k = 0; k < 64; k++) {
        float w1v = w1_s[l][k], w2v = w2_s[l][k];
        float h0 = hr0[k], h1 = hr1[k];
        e10 = fmaf(h0, w1v, e10);
        e20 = fmaf(h0, w2v, e20);
        e11 = fmaf(h1, w1v, e11);
        e21 = fmaf(h1, w2v, e21);
    }
    g_e1[n0 * 32 + l] = e10;
    g_e2[n0 * 32 + l] = e20;
    g_e1[n1 * 32 + l] = e11;
    g_e2[n1 * 32 + l] = e21;
}

// ---------------- K2: attention, branch-free rescaled elu ----------------
__global__ void __launch_bounds__(256) attn_kernel(
    const float* __restrict__ b1, const float* __restrict__ V,
    const float* __restrict__ bv) {
    int b  = blockIdx.z;
    int i0 = blockIdx.y * 64, j0 = blockIdx.x * 64;
    __shared__ float e2s[64][33], e1s[64][33];
    __shared__ float part[16][65];
    __shared__ float Vs[32];
    int tid = threadIdx.x;
    if (tid < 32) Vs[tid] = V[tid];
#pragma unroll
    for (int it = 0; it < 2; it++) {
        int idx = tid + it * 256;          // 0..511
        int r = idx >> 3, c4 = (idx & 7) * 4;
        float4 v2 = *(const float4*)&g_e2[(b * 512 + i0 + r) * 32 + c4];
        float4 vb = *(const float4*)&b1[c4];
        e2s[r][c4 + 0] = (v2.x + vb.x) * LOG2E;
        e2s[r][c4 + 1] = (v2.y + vb.y) * LOG2E;
        e2s[r][c4 + 2] = (v2.z + vb.z) * LOG2E;
        e2s[r][c4 + 3] = (v2.w + vb.w) * LOG2E;
        float4 v1 = *(const float4*)&g_e1[(b * 512 + j0 + r) * 32 + c4];
        e1s[r][c4 + 0] = v1.x * LOG2E; e1s[r][c4 + 1] = v1.y * LOG2E;
        e1s[r][c4 + 2] = v1.z * LOG2E; e1s[r][c4 + 3] = v1.w * LOG2E;
    }
    __syncthreads();

    float sumV = 0.0f;
#pragma unroll
    for (int h = 0; h < 32; h++) sumV += Vs[h];

    int tx = tid & 15, ty = tid >> 4;
    float accM[4][4], accE[4][4];
#pragma unroll
    for (int u = 0; u < 4; u++)
#pragma unroll
        for (int v = 0; v < 4; v++) { accM[u][v] = 0.0f; accE[u][v] = 0.0f; }

#pragma unroll 4
    for (int h = 0; h < 32; h++) {
        float av[4], bw[4], vh = Vs[h];
#pragma unroll
        for (int u = 0; u < 4; u++) av[u] = e2s[ty * 4 + u][h];
#pragma unroll
        for (int v = 0; v < 4; v++) bw[v] = e1s[tx * 4 + v][h];
#pragma unroll
        for (int u = 0; u < 4; u++)
#pragma unroll
            for (int v = 0; v < 4; v++) {
                float t = av[u] + bw[v];             // scaled by log2e
                float tp = fmaxf(t, 0.0f);
                float tn = fminf(t, 0.0f);
                float ex = ex2f(tn);
                accM[u][v] = fmaf(tp, vh, accM[u][v]);
                accE[u][v] = fmaf(ex, vh, accE[u][v]);
            }
    }
    float bias2 = bv[0] - sumV;
    float sq[4] = {0.0f, 0.0f, 0.0f, 0.0f};
#pragma unroll
    for (int u = 0; u < 4; u++) {
        float4 o;
        o.x = fmaf(accM[u][0], LN2, accE[u][0]) + bias2;
        o.y = fmaf(accM[u][1], LN2, accE[u][1]) + bias2;
        o.z = fmaf(accM[u][2], LN2, accE[u][2]) + bias2;
        o.w = fmaf(accM[u][3], LN2, accE[u][3]) + bias2;
        sq[0] = fmaf(o.x, o.x, sq[0]); sq[1] = fmaf(o.y, o.y, sq[1]);
        sq[2] = fmaf(o.z, o.z, sq[2]); sq[3] = fmaf(o.w, o.w, sq[3]);
        int i = i0 + ty * 4 + u;
        *(float4*)&g_amx[(b * 512 + i) * 512 + j0 + tx * 4] = o;
    }
#pragma unroll
    for (int v = 0; v < 4; v++) part[ty][tx * 4 + v] = sq[v];
    __syncthreads();
    if (tid < 64) {
        float s = 0.0f;
#pragma unroll
        for (int r = 0; r < 16; r++) s += part[r][tid];
        g_colsq_part[blockIdx.y][b * 512 + j0 + tid] = s;   // no atomics
    }
}

// ---------------- K3: inverse column norms (sum 8 partials) ----------------
__global__ void invnorm_kernel() {
    int i = blockIdx.x * 256 + threadIdx.x;
    float s = 0.0f;
#pragma unroll
    for (int r = 0; r < 8; r++) s += g_colsq_part[r][i];
    g_invn[i] = 1.0f / fmaxf(sqrtf(s), 1e-12f);
}

// ---------------- K5: tf32 mma.sync GEMM, double-buffered smem pipeline ----------------
#define APITCH 20
#define BPITCH 132
__global__ void __launch_bounds__(256) gemm_tc_kernel(
    const float* __restrict__ Wb, const float* __restrict__ wb,
    const float* __restrict__ adj) {
    __shared__ float As_hi[2][128][APITCH];
    __shared__ float Bs_hi[2][16][BPITCH];
    __shared__ float inv_sh[512];
    int tid = threadIdx.x;
    int n0 = blockIdx.y * 128, j0 = blockIdx.x * 128;
    int b = blockIdx.y >> 2;
    int wid = tid >> 5, lane = tid & 31;
    int warp_row = (wid >> 2) * 64;   // 0 or 64
    int warp_col = (wid & 3) * 32;    // 0..96
    int group = lane >> 2, tig = lane & 3;

    for (int t = tid; t < 512; t += 256) inv_sh[t] = g_invn[b * 512 + t];

    float c[4][4][4];
#pragma unroll
    for (int mt = 0; mt < 4; mt++)
#pragma unroll
        for (int nt = 0; nt < 4; nt++)
#pragma unroll
            for (int q = 0; q < 4; q++) c[mt][nt][q] = 0.0f;

    int ar0 = tid >> 2, ac4 = (tid & 3) * 4;
    int br0 = tid >> 5, bc4 = (tid & 31) * 4;
    // preload tile 0
    float4 vah0 = *(const float4*)&g_amx[(n0 + ar0) * 512 + ac4];
    float4 vah1 = *(const float4*)&g_amx[(n0 + ar0 + 64) * 512 + ac4];
    float4 vbh0 = *(const float4*)&Wb[br0 * 512 + j0 + bc4];
    float4 vbh1 = *(const float4*)&Wb[(br0 + 8) * 512 + j0 + bc4];
    __syncthreads();   // inv_sh ready
    {
        float4 iv = *(const float4*)&inv_sh[ac4];
        As_hi[0][ar0][ac4 + 0]      = f2tf32f(vah0.x * iv.x);
        As_hi[0][ar0][ac4 + 1]      = f2tf32f(vah0.y * iv.y);
        As_hi[0][ar0][ac4 + 2]      = f2tf32f(vah0.z * iv.z);
        As_hi[0][ar0][ac4 + 3]      = f2tf32f(vah0.w * iv.w);
        As_hi[0][ar0 + 64][ac4 + 0] = f2tf32f(vah1.x * iv.x);
        As_hi[0][ar0 + 64][ac4 + 1] = f2tf32f(vah1.y * iv.y);
        As_hi[0][ar0 + 64][ac4 + 2] = f2tf32f(vah1.z * iv.z);
        As_hi[0][ar0 + 64][ac4 + 3] = f2tf32f(vah1.w * iv.w);
        Bs_hi[0][br0][bc4 + 0]      = f2tf32f(vbh0.x);
        Bs_hi[0][br0][bc4 + 1]      = f2tf32f(vbh0.y);
        Bs_hi[0][br0][bc4 + 2]      = f2tf32f(vbh0.z);
        Bs_hi[0][br0][bc4 + 3]      = f2tf32f(vbh0.w);
        Bs_hi[0][br0 + 8][bc4 + 0]  = f2tf32f(vbh1.x);
        Bs_hi[0][br0 + 8][bc4 + 1]  = f2tf32f(vbh1.y);
        Bs_hi[0][br0 + 8][bc4 + 2]  = f2tf32f(vbh1.z);
        Bs_hi[0][br0 + 8][bc4 + 3]  = f2tf32f(vbh1.w);
    }
    __syncthreads();

    for (int kt = 0; kt < 32; kt++) {
        int cur = kt & 1;
        // issue next tile's global loads first (latency hidden under MMAs)
        if (kt < 31) {
            int kn = (kt + 1) * 16;
            vah0 = *(const float4*)&g_amx[(n0 + ar0) * 512 + kn + ac4];
            vah1 = *(const float4*)&g_amx[(n0 + ar0 + 64) * 512 + kn + ac4];
            vbh0 = *(const float4*)&Wb[(kn + br0) * 512 + j0 + bc4];
            vbh1 = *(const float4*)&Wb[(kn + br0 + 8) * 512 + j0 + bc4];
        }
#pragma unroll
        for (int s = 0; s < 2; s++) {
            int ks = s * 8;
            uint32_t bh[4][2];
#pragma unroll
            for (int nt = 0; nt < 4; nt++) {
                int nn = warp_col + nt * 8 + group;
                bh[nt][0] = __float_as_uint(Bs_hi[cur][ks + tig][nn]);
                bh[nt][1] = __float_as_uint(Bs_hi[cur][ks + tig + 4][nn]);
            }
#pragma unroll
            for (int mt = 0; mt < 4; mt++) {
                int rr = warp_row + mt * 16 + group;
                uint32_t ah0 = __float_as_uint(As_hi[cur][rr][ks + tig]);
                uint32_t ah1 = __float_as_uint(As_hi[cur][rr + 8][ks + tig]);
                uint32_t ah2 = __float_as_uint(As_hi[cur][rr][ks + tig + 4]);
                uint32_t ah3 = __float_as_uint(As_hi[cur][rr + 8][ks + tig + 4]);
#pragma unroll
                for (int nt = 0; nt < 4; nt++)
                    mma_tf32(c[mt][nt], ah0, ah1, ah2, ah3, bh[nt][0], bh[nt][1]);
            }
        }
        // store prefetched tile into the other buffer while MMAs drain
        if (kt < 31) {
            int nb = cur ^ 1;
            float4 iv = *(const float4*)&inv_sh[(kt + 1) * 16 + ac4];
            As_hi[nb][ar0][ac4 + 0]      = f2tf32f(vah0.x * iv.x);
            As_hi[nb][ar0][ac4 + 1]      = f2tf32f(vah0.y * iv.y);
            As_hi[nb][ar0][ac4 + 2]      = f2tf32f(vah0.z * iv.z);
            As_hi[nb][ar0][ac4 + 3]      = f2tf32f(vah0.w * iv.w);
            As_hi[nb][ar0 + 64][ac4 + 0] = f2tf32f(vah1.x * iv.x);
            As_hi[nb][ar0 + 64][ac4 + 1] = f2tf32f(vah1.y * iv.y);
            As_hi[nb][ar0 + 64][ac4 + 2] = f2tf32f(vah1.z * iv.z);
            As_hi[nb][ar0 + 64][ac4 + 3] = f2tf32f(vah1.w * iv.w);
            Bs_hi[nb][br0][bc4 + 0]      = f2tf32f(vbh0.x);
            Bs_hi[nb][br0][bc4 + 1]      = f2tf32f(vbh0.y);
            Bs_hi[nb][br0][bc4 + 2]      = f2tf32f(vbh0.z);
            Bs_hi[nb][br0][bc4 + 3]      = f2tf32f(vbh0.w);
            Bs_hi[nb][br0 + 8][bc4 + 0]  = f2tf32f(vbh1.x);
            Bs_hi[nb][br0 + 8][bc4 + 1]  = f2tf32f(vbh1.y);
            Bs_hi[nb][br0 + 8][bc4 + 2]  = f2tf32f(vbh1.z);
            Bs_hi[nb][br0 + 8][bc4 + 3]  = f2tf32f(vbh1.w);
        }
        __syncthreads();
    }

    float wbv = wb[0];
#pragma unroll
    for (int mt = 0; mt < 4; mt++) {
#pragma unroll
        for (int nt = 0; nt < 4; nt++) {
            int col = j0 + warp_col + nt * 8 + tig * 2;
            float i0v = inv_sh[col], i1v = inv_sh[col + 1];
#pragma unroll
            for (int half = 0; half < 2; half++) {
                int row = n0 + warp_row + mt * 16 + group + half * 8;
                float d0 = c[mt][nt][half * 2 + 0];
                float d1 = c[mt][nt][half * 2 + 1];
                float2 am = *(const float2*)&g_amx[row * 512 + col];
                float2 ad = *(const float2*)&adj[(row & 511) * 512 + col];
                float s0 = 1.0f / (1.0f + __expf(-(d0 + wbv)));
                float s1 = 1.0f / (1.0f + __expf(-(d1 + wbv)));
                float2 o;
                o.x = fmaf(ad.x, s0, am.x * i0v * (1.0f - s0));
                o.y = fmaf(ad.y, s1, am.y * i1v * (1.0f - s1));
                *(float2*)&g_adjmix[row * 512 + col] = o;
            }
        }
    }
}

// ---------------- K6: fused conv features + rg = relu(r) @ gc1_w ----------------
__global__ void __launch_bounds__(256) convrg_kernel(
    const float* __restrict__ x, const float* __restrict__ conv_w,
    const float* __restrict__ conv_b, const float* __restrict__ convl_w,
    const float* __restrict__ convl_b, const float* __restrict__ gc1_w) {
    __shared__ float cw[256], clw[128], cb[8], clb[8];
    __shared__ float seq[4][32];
    __shared__ float r_sh[4][24];
    __shared__ float g1s[24 * 64];
    int tid = threadIdx.x;
    cw[tid] = conv_w[tid];
    if (tid < 128) clw[tid] = convl_w[tid];
    if (tid < 8) { cb[tid] = conv_b[tid]; clb[tid] = convl_b[tid]; }
    for (int t = tid; t < 24 * 64; t += 256) g1s[t] = gc1_w[t];
    if (tid < 128) {
        int gg = tid >> 5, t = tid & 31;
        int nn = blockIdx.x * 4 + gg;
        seq[gg][t] = x[((nn >> 9) * WW + t) * MM + (nn & 511)];
    }
    __syncthreads();

    if (tid < 96) {
        int g = tid / 24, idx = tid % 24;
        int kk = idx / 3, cc = idx % 3;
        float a;
        if (cc == 0) {
            a = cb[kk];
#pragma unroll
            for (int t = 0; t < 32; t++) a = fmaf(seq[g][t], cw[kk * 32 + t], a);
        } else {
            a = clb[kk];
#pragma unroll
            for (int i = 0; i < 16; i++)
                a = fmaf(seq[g][2 * i + (cc - 1)], clw[kk * 16 + i], a);
        }
        r_sh[g][idx] = fmaxf(a, 0.0f);
    }
    __syncthreads();

    int g = tid >> 6, j = tid & 63;
    int n = blockIdx.x * 4 + g;
    float acc = 0.0f;
#pragma unroll
    for (int idx = 0; idx < 24; idx++)
        acc = fmaf(r_sh[g][idx], g1s[idx * 64 + j], acc);
    g_rg[n * 64 + j] = acc;
}

// ---------------- K8: h1 = relu(adj_mix @ rg + gc1_b); fused h1g = h1 @ gc2_w ----------------
__global__ void __launch_bounds__(256) h1_kernel(
    const float* __restrict__ gc1_b, const float* __restrict__ gc2_w) {
    __shared__ __align__(16) float As[16][68];
    __shared__ __align__(16) float Bs[16][68];
    __shared__ float h1s[64][65];
    __shared__ float g2s[640];
    int tid = threadIdx.x;
    int bb = blockIdx.y;
    int i0 = blockIdx.x * 64;
    int tx = tid & 15, ty = tid >> 4;
    float acc[4][4];
#pragma unroll
    for (int u = 0; u < 4; u++)
#pragma unroll
        for (int v = 0; v < 4; v++) acc[u][v] = 0.0f;
    for (int t = tid; t < 640; t += 256) g2s[t] = gc2_w[t];

    int arow = tid >> 2, ac4 = (tid & 3) * 4;
    int brow = tid >> 4, bc4 = (tid & 15) * 4;
    float4 av  = *(const float4*)&g_adjmix[(bb * 512 + i0 + arow) * 512 + ac4];
    float4 bvv = *(const float4*)&g_rg[(bb * 512 + brow) * 64 + bc4];
    for (int kt = 0; kt < 32; kt++) {
        __syncthreads();
        As[ac4 + 0][arow] = av.x; As[ac4 + 1][arow] = av.y;
        As[ac4 + 2][arow] = av.z; As[ac4 + 3][arow] = av.w;
        *(float4*)&Bs[brow][bc4] = bvv;
        __syncthreads();
        if (kt < 31) {
            int k0 = (kt + 1) * 16;
            av  = *(const float4*)&g_adjmix[(bb * 512 + i0 + arow) * 512 + k0 + ac4];
            bvv = *(const float4*)&g_rg[(bb * 512 + k0 + brow) * 64 + bc4];
        }
#pragma unroll
        for (int k = 0; k < 16; k++) {
            float4 a = *(const float4*)&As[k][ty * 4];
            float4 b = *(const float4*)&Bs[k][tx * 4];
            float a_[4] = {a.x, a.y, a.z, a.w};
            float b_[4] = {b.x, b.y, b.z, b.w};
#pragma unroll
            for (int u = 0; u < 4; u++)
#pragma unroll
                for (int v = 0; v < 4; v++)
                    acc[u][v] = fmaf(a_[u], b_[v], acc[u][v]);
        }
    }
    __syncthreads();
#pragma unroll
    for (int u = 0; u < 4; u++)
#pragma unroll
        for (int v = 0; v < 4; v++)
            h1s[ty * 4 + u][tx * 4 + v] = fmaxf(acc[u][v] + gc1_b[tx * 4 + v], 0.0f);
    __syncthreads();
    for (int idx = tid; idx < 640; idx += 256) {
        int i = idx & 63, jj = idx >> 6;
        float a = 0.0f;
#pragma unroll
        for (int j = 0; j < 64; j++) a = fmaf(h1s[i][j], g2s[j * 10 + jj], a);
        g_h1g[(bb * 512 + i0 + i) * 10 + jj] = a;
    }
}

// ---------------- K9: out_spatial + fused output head ----------------
__global__ void __launch_bounds__(640) out_kernel(
    const float* __restrict__ gc2_b, const float* __restrict__ out_w,
    const float* __restrict__ out_b, float* __restrict__ out) {
    __shared__ float adjs[64][65];
    __shared__ float hgs[64][12];
    __shared__ float oss[64][13];
    __shared__ float hids[64][65];
    __shared__ float ows[592];
    __shared__ float gbs[10], obs[8];
    int tid = threadIdx.x;
    int bb = blockIdx.y;
    int i0 = blockIdx.x * 64;
    for (int t = tid; t < 592; t += 640) ows[t] = out_w[t];
    if (tid < 10) gbs[tid] = gc2_b[tid];
    if (tid < 8)  obs[tid] = out_b[tid];

    int il = tid / 10;
    int jj = tid % 10;
    float acc = 0.0f;
    for (int kt = 0; kt < 8; kt++) {
        __syncthreads();
        for (int idx = tid; idx < 4096; idx += 640) {
            int r = idx >> 6, cc = idx & 63;
            adjs[r][cc] = g_adjmix[(bb * 512 + i0 + r) * 512 + kt * 64 + cc];
        }
        {
            int kr = tid / 10, j2 = tid % 10;
            hgs[kr][j2] = g_h1g[(bb * 512 + kt * 64 + kr) * 10 + j2];
        }
        __syncthreads();
#pragma unroll 8
        for (int k = 0; k < 64; k++) acc = fmaf(adjs[il][k], hgs[k][jj], acc);
    }
    __syncthreads();
    oss[il][jj] = fmaxf(acc + gbs[jj], 0.0f);
    for (int idx = tid; idx < 4096; idx += 640) {
        int r = idx >> 6, cc = idx & 63;
        hids[r][cc] = g_hid[(bb * 512 + i0 + r) * 64 + cc];
    }
    __syncthreads();
    if (tid < 512) {
        int h = tid >> 6, i = tid & 63;
        float a = obs[h];
#pragma unroll
        for (int q = 0; q < 10; q++) a = fmaf(oss[i][q], ows[h * 74 + q], a);
#pragma unroll
        for (int t = 0; t < 64; t++) a = fmaf(hids[i][t], ows[h * 74 + 10 + t], a);
        out[bb * 4096 + h * 512 + i0 + i] = a;
    }
}

// ---------------- launch ----------------
extern "C" void kernel_launch(void* const* d_in, const int* in_sizes, int n_in,
                              void* d_out, int out_size) {
    const float* x       = (const float*)d_in[0];
    const float* adj     = (const float*)d_in[1];
    const float* Wih     = (const float*)d_in[2];
    const float* Whh     = (const float*)d_in[3];
    const float* bih     = (const float*)d_in[4];
    const float* bhh     = (const float*)d_in[5];
    const float* W1      = (const float*)d_in[6];
    const float* W2      = (const float*)d_in[7];
    const float* b1      = (const float*)d_in[8];
    const float* V       = (const float*)d_in[9];
    const float* bv      = (const float*)d_in[10];
    const float* Wb      = (const float*)d_in[11];
    const float* wb      = (const float*)d_in[12];
    const float* conv_w  = (const float*)d_in[13];
    const float* conv_b  = (const float*)d_in[14];
    const float* convl_w = (const float*)d_in[15];
    const float* convl_b = (const float*)d_in[16];
    const float* gc1_w   = (const float*)d_in[17];
    const float* gc1_b   = (const float*)d_in[18];
    const float* gc2_w   = (const float*)d_in[19];
    const float* gc2_b   = (const float*)d_in[20];
    const float* out_w   = (const float*)d_in[21];
    const float* out_b   = (const float*)d_in[22];
    float* out = (float*)d_out;

    // gemm_tc in profiled slot (#4), now double-buffered.
    rnn_kernel<<<1024, 128>>>(x, Wih, Whh, bih, bhh, W1, W2);
    attn_kernel<<<dim3(8, 8, 16), 256>>>(b1, V, bv);
    invnorm_kernel<<<32, 256>>>();
    gemm_tc_kernel<<<dim3(4, 64), 256>>>(Wb, wb, adj);
    convrg_kernel<<<2048, 256>>>(x, conv_w, conv_b, convl_w, convl_b, gc1_w);
    h1_kernel<<<dim3(8, 16), 256>>>(gc1_b, gc2_w);
    out_kernel<<<dim3(8, 16), 640>>>(gc2_b, out_w, out_b, out);
}